// round 7
// baseline (speedup 1.0000x reference)
#include <cuda_runtime.h>
#include <cuda_bf16.h>

#define BATCH 512
#define TLEN  256
#define HID   512
#define G4    2048
#define HALF  256
#define TGT   28

#define NTHREADS 128
#define NCTAS 128
#define GSZ (NCTAS * NTHREADS)
#define WSMEM_BYTES 131072   // 32 k16 x 8 n8 x 512B (hi+lo W fragments)

// ---------------- device scratch ----------------
// A(h) fragments per (m16,k16): 1024B = [hi: lane*16][lo: +512 + lane*16]
__device__ __align__(16) unsigned char g_hfrag[2][1 << 20];
// B(W) fragments per (n8,k16): 512B = lane*16 : {hi_r0, hi_r1, lo_r0, lo_r1}
__device__ __align__(16) unsigned char g_Wfrag[4 << 20];
__device__ __align__(16) float g_hfin[BATCH * HID];
__device__ __align__(16) float g_hid[BATCH * HALF];
__device__ unsigned int g_barcnt;
__device__ volatile unsigned int g_bargen;

__device__ __forceinline__ void gridbar() {
    __threadfence();
    __syncthreads();
    if (threadIdx.x == 0) {
        unsigned int gen = g_bargen;
        if (atomicAdd(&g_barcnt, 1u) == NCTAS - 1u) {
            g_barcnt = 0u;
            __threadfence();
            g_bargen = gen + 1u;
        } else {
            while (g_bargen == gen) { }
            __threadfence();
        }
    }
    __syncthreads();
}

__device__ __forceinline__ float sigf(float x)  { return 1.0f / (1.0f + __expf(-x)); }
__device__ __forceinline__ float tanhft(float x){ return 1.0f - 2.0f / (__expf(2.0f * x) + 1.0f); }

__device__ __forceinline__ unsigned int pack2(float a, float b) {
    __nv_bfloat16 ah = __float2bfloat16(a), bh = __float2bfloat16(b);
    return (unsigned int)__bfloat16_as_ushort(ah) |
           ((unsigned int)__bfloat16_as_ushort(bh) << 16);
}

#define MMA_BF16(c, A, B0, B1)                                              \
    asm volatile("mma.sync.aligned.m16n8k16.row.col.f32.bf16.bf16.f32 "     \
                 "{%0,%1,%2,%3}, {%4,%5,%6,%7}, {%8,%9}, {%0,%1,%2,%3};"    \
                 : "+f"(c[0]), "+f"(c[1]), "+f"(c[2]), "+f"(c[3])           \
                 : "r"(A.x), "r"(A.y), "r"(A.z), "r"(A.w), "r"(B0), "r"(B1))

__global__ __launch_bounds__(NTHREADS, 1)
void lstm_mma_kernel(
    const float* __restrict__ seq,  const float* __restrict__ W_ih,
    const float* __restrict__ W_hh, const float* __restrict__ b_ih,
    const float* __restrict__ b_hh, const float* __restrict__ fc1w,
    const float* __restrict__ fc1b, const float* __restrict__ fc2w,
    const float* __restrict__ fc2b, float* __restrict__ out)
{
    extern __shared__ unsigned char wsm[];                 // 128KB W fragments
    __shared__ __align__(16) float stage[8][16][18];       // h repack tile (per m16 band)
    __shared__ __align__(16) float4 sm_wih[16], sm_bias[16];
    __shared__ __align__(16) float hs[4][HID];             // fc1 tail

    const int tid  = threadIdx.x;
    const int cta  = blockIdx.x;
    const int gid  = cta * NTHREADS + tid;
    const int lane = tid & 31;
    const int wti  = tid >> 5;          // warp 0..3, owns m16 bands {2w, 2w+1}
    const int gq   = lane >> 2;
    const int tg   = lane & 3;

    // ---- prep: W fragments (split + gate-interleave reorder) ----
    for (int it = gid; it < 256 * 32 * 32; it += GSZ) {
        int ln  = it & 31;               // == lane (stride multiple of 32)
        int k16 = (it >> 5) & 31;
        int n8  = it >> 10;
        int n   = n8 * 8 + (ln >> 2);
        int w16 = n & 15;
        int gate = ((w16 >> 3) << 1) | (w16 & 1);
        int unit = (n >> 4) * 4 + ((w16 & 7) >> 1);
        const float* wr = W_hh + (gate * HID + unit) * HID + k16 * 16 + ((ln & 3) << 1);
        float2 p0 = *(const float2*)wr;
        float2 p1 = *(const float2*)(wr + 8);
        float h0x = __bfloat162float(__float2bfloat16(p0.x));
        float h0y = __bfloat162float(__float2bfloat16(p0.y));
        float h1x = __bfloat162float(__float2bfloat16(p1.x));
        float h1y = __bfloat162float(__float2bfloat16(p1.y));
        uint4 v;
        v.x = pack2(p0.x, p0.y);
        v.y = pack2(p1.x, p1.y);
        v.z = pack2(p0.x - h0x, p0.y - h0y);
        v.w = pack2(p1.x - h1x, p1.y - h1y);
        *(uint4*)(g_Wfrag + (((n8 << 5) + k16) << 9) + ln * 16) = v;
    }
    {
        uint4 z = make_uint4(0, 0, 0, 0);
        uint4* hz = (uint4*)g_hfrag[0];
        for (int e = gid; e < (1 << 16); e += GSZ) hz[e] = z;
    }
    gridbar();

    // ---- per-CTA geometry ----
    const int tileM = cta >> 5;            // 0..3
    const int tileN = cta & 31;            // 0..31
    const int b0    = tileM * 128;
    const int m16g0 = tileM * 8 + wti * 2; // first band of this warp

    // copy this CTA's W fragments to smem (once; k16-major)
    {
        uint4* s4 = (uint4*)wsm;
        const uint4* g4 = (const uint4*)g_Wfrag;
        for (int e = tid; e < WSMEM_BYTES / 16; e += NTHREADS) {
            int w = e & 31, c = e >> 5;
            int kt = c >> 3, j = c & 7;
            s4[e] = __ldcg(&g4[(((tileN * 8 + j) << 5) + kt) * 32 + w]);
        }
    }
    for (int e = tid; e < 64; e += NTHREADS) {
        int u = e >> 2, g = e & 3;
        int ku = tileN * 16 + u;
        ((float*)sm_wih)[e]  = W_ih[g * HID + ku];
        ((float*)sm_bias)[e] = b_ih[g * HID + ku] + b_hh[g * HID + ku];
    }
    __syncthreads();

    float creg[2][2][4];                   // [band][rh][unit-jj]
    #pragma unroll
    for (int b = 0; b < 2; ++b)
        #pragma unroll
        for (int r = 0; r < 2; ++r)
            #pragma unroll
            for (int j = 0; j < 4; ++j) creg[b][r][j] = 0.0f;

    // ---- recurrent loop ----
    for (int t = 0; t < TLEN; ++t) {
        const unsigned char* hin  = g_hfrag[t & 1];
        unsigned char*       hout = g_hfrag[(t + 1) & 1];
        const unsigned char* abase0 = hin + ((size_t)(m16g0 * 32) << 10) + lane * 16;
        const unsigned char* abase1 = abase0 + (32 << 10);   // band +1

        float acc[2][8][4];
        #pragma unroll
        for (int b = 0; b < 2; ++b)
            #pragma unroll
            for (int j = 0; j < 8; ++j)
                #pragma unroll
                for (int c = 0; c < 4; ++c) acc[b][j][c] = 0.0f;

        uint4 ah[2][2], al[2][2];          // [band][slot]
        ah[0][0] = __ldcg((const uint4*)(abase0));
        al[0][0] = __ldcg((const uint4*)(abase0 + 512));
        ah[1][0] = __ldcg((const uint4*)(abase1));
        al[1][0] = __ldcg((const uint4*)(abase1 + 512));
        ah[0][1] = __ldcg((const uint4*)(abase0 + 1024));
        al[0][1] = __ldcg((const uint4*)(abase0 + 1536));
        ah[1][1] = __ldcg((const uint4*)(abase1 + 1024));
        al[1][1] = __ldcg((const uint4*)(abase1 + 1536));

        #pragma unroll 2
        for (int kt = 0; kt < 32; ++kt) {
            const int s = kt & 1;
            uint4 bw[8];
            #pragma unroll
            for (int j = 0; j < 8; ++j)
                bw[j] = *(const uint4*)(wsm + (((kt << 3) + j) << 9) + lane * 16);
            // term 1: h_hi * w_hi   (acc reuse distance = 16 MMAs)
            #pragma unroll
            for (int j = 0; j < 8; ++j) MMA_BF16(acc[0][j], ah[0][s], bw[j].x, bw[j].y);
            #pragma unroll
            for (int j = 0; j < 8; ++j) MMA_BF16(acc[1][j], ah[1][s], bw[j].x, bw[j].y);
            // term 2: h_lo * w_hi
            #pragma unroll
            for (int j = 0; j < 8; ++j) MMA_BF16(acc[0][j], al[0][s], bw[j].x, bw[j].y);
            #pragma unroll
            for (int j = 0; j < 8; ++j) MMA_BF16(acc[1][j], al[1][s], bw[j].x, bw[j].y);
            // term 3: h_hi * w_lo
            #pragma unroll
            for (int j = 0; j < 8; ++j) MMA_BF16(acc[0][j], ah[0][s], bw[j].z, bw[j].w);
            #pragma unroll
            for (int j = 0; j < 8; ++j) MMA_BF16(acc[1][j], ah[1][s], bw[j].z, bw[j].w);
            if (kt + 2 < 32) {
                const unsigned char* p0 = abase0 + ((size_t)(kt + 2) << 10);
                const unsigned char* p1 = abase1 + ((size_t)(kt + 2) << 10);
                ah[0][s] = __ldcg((const uint4*)p0);
                al[0][s] = __ldcg((const uint4*)(p0 + 512));
                ah[1][s] = __ldcg((const uint4*)p1);
                al[1][s] = __ldcg((const uint4*)(p1 + 512));
            }
        }

        // ---- epilogue: gates -> c,h ; repack h into A fragments ----
        #pragma unroll
        for (int b = 0; b < 2; ++b) {
            const int row_base = b0 + (m16g0 - tileM * 8 + b) * 16 + gq; // local band rows
            #pragma unroll
            for (int rh = 0; rh < 2; ++rh) {
                float xv = seq[(row_base + rh * 8) * TLEN + t];
                #pragma unroll
                for (int jj = 0; jj < 4; ++jj) {
                    float4 wv = sm_wih[jj * 4 + tg];
                    float4 bv = sm_bias[jj * 4 + tg];
                    float gi = acc[b][2*jj  ][rh*2+0] + xv * wv.x + bv.x;
                    float gf = acc[b][2*jj  ][rh*2+1] + xv * wv.y + bv.y;
                    float gg = acc[b][2*jj+1][rh*2+0] + xv * wv.z + bv.z;
                    float go = acc[b][2*jj+1][rh*2+1] + xv * wv.w + bv.w;
                    float cc = sigf(gf) * creg[b][rh][jj] + sigf(gi) * tanhft(gg);
                    creg[b][rh][jj] = cc;
                    float hv = sigf(go) * tanhft(cc);
                    stage[wti * 2 + b][gq + rh * 8][jj * 4 + tg] = hv;
                    if (t == TLEN - 1)
                        g_hfin[(row_base + rh * 8) * HID + tileN * 16 + jj * 4 + tg] = hv;
                }
            }
        }
        __syncwarp();
        #pragma unroll
        for (int b = 0; b < 2; ++b) {
            unsigned int fhi[4], flo[4];
            #pragma unroll
            for (int r = 0; r < 4; ++r) {
                int m  = gq + (r & 1) * 8;
                int k0 = tg * 2 + (r >> 1) * 8;
                float a = stage[wti * 2 + b][m][k0];
                float bb = stage[wti * 2 + b][m][k0 + 1];
                float ahh = __bfloat162float(__float2bfloat16(a));
                float bhh = __bfloat162float(__float2bfloat16(bb));
                fhi[r] = pack2(a, bb);
                flo[r] = pack2(a - ahh, bb - bhh);
            }
            unsigned char* op = hout + ((size_t)((m16g0 + b) * 32 + tileN) << 10) + lane * 16;
            *(uint4*)op         = make_uint4(fhi[0], fhi[1], fhi[2], fhi[3]);
            *(uint4*)(op + 512) = make_uint4(flo[0], flo[1], flo[2], flo[3]);
        }

        gridbar();
    }

    // ---- fc1: hid = relu(h @ fc1w^T + fc1b), 4 batch rows per CTA ----
    {
        int bb = cta * 4;
        for (int e = tid; e < 4 * HID; e += NTHREADS)
            hs[e >> 9][e & 511] = g_hfin[(bb + (e >> 9)) * HID + (e & 511)];
        __syncthreads();
        for (int n = tid; n < HALF; n += NTHREADS) {
            const float* wr = fc1w + n * HID;
            float s0 = fc1b[n], s1 = s0, s2 = s0, s3 = s0;
            #pragma unroll 8
            for (int k = 0; k < HID; ++k) {
                float w = wr[k];
                s0 += hs[0][k] * w; s1 += hs[1][k] * w;
                s2 += hs[2][k] * w; s3 += hs[3][k] * w;
            }
            g_hid[(bb + 0) * HALF + n] = fmaxf(s0, 0.0f);
            g_hid[(bb + 1) * HALF + n] = fmaxf(s1, 0.0f);
            g_hid[(bb + 2) * HALF + n] = fmaxf(s2, 0.0f);
            g_hid[(bb + 3) * HALF + n] = fmaxf(s3, 0.0f);
        }
    }
    gridbar();

    // ---- fc2 ----
    for (int o = gid; o < BATCH * TGT; o += GSZ) {
        int b = o / TGT;
        int tt = o - b * TGT;
        const float* hr = g_hid + b * HALF;
        const float* wr = fc2w + tt * HALF;
        float s = fc2b[tt];
        #pragma unroll 8
        for (int k = 0; k < HALF; ++k) s += hr[k] * wr[k];
        out[o] = s;
    }
}

extern "C" void kernel_launch(void* const* d_in, const int* in_sizes, int n_in,
                              void* d_out, int out_size) {
    (void)in_sizes; (void)n_in; (void)out_size;
    cudaFuncSetAttribute(lstm_mma_kernel,
                         cudaFuncAttributeMaxDynamicSharedMemorySize, WSMEM_BYTES);
    lstm_mma_kernel<<<NCTAS, NTHREADS, WSMEM_BYTES>>>(
        (const float*)d_in[0], (const float*)d_in[1], (const float*)d_in[2],
        (const float*)d_in[3], (const float*)d_in[4], (const float*)d_in[5],
        (const float*)d_in[6], (const float*)d_in[7], (const float*)d_in[8],
        (float*)d_out);
}

// round 8
// speedup vs baseline: 1.2936x; 1.2936x over previous
#include <cuda_runtime.h>
#include <cuda_bf16.h>

#define BATCH 512
#define TLEN  256
#define HID   512
#define G4    2048
#define HALF  256
#define TGT   28

#define NTHREADS 256
#define NCTAS 128
#define GSZ (NCTAS * NTHREADS)
#define WSMEM_BYTES 131072   // 32 k16 x 8 n8 x 512B (hi+lo W fragments)

// ---------------- device scratch ----------------
// A(h) fragments per (m16,k16): 1024B = [hi: lane*16][lo: +512 + lane*16]
__device__ __align__(16) unsigned char g_hfrag[2][1 << 20];
// B(W) fragments per (n8,k16): 512B = lane*16 : {hi_r0, hi_r1, lo_r0, lo_r1}
__device__ __align__(16) unsigned char g_Wfrag[4 << 20];
__device__ __align__(16) float g_hfin[BATCH * HID];
__device__ __align__(16) float g_hid[BATCH * HALF];
__device__ unsigned int g_barcnt;
__device__ volatile unsigned int g_bargen;

__device__ __forceinline__ void gridbar() {
    __threadfence();
    __syncthreads();
    if (threadIdx.x == 0) {
        unsigned int gen = g_bargen;
        if (atomicAdd(&g_barcnt, 1u) == NCTAS - 1u) {
            g_barcnt = 0u;
            __threadfence();
            g_bargen = gen + 1u;
        } else {
            while (g_bargen == gen) { }
            __threadfence();
        }
    }
    __syncthreads();
}

__device__ __forceinline__ float sigf(float x)  { return 1.0f / (1.0f + __expf(-x)); }
__device__ __forceinline__ float tanhft(float x){ return 1.0f - 2.0f / (__expf(2.0f * x) + 1.0f); }

__device__ __forceinline__ unsigned int pack2(float a, float b) {
    __nv_bfloat16 ah = __float2bfloat16(a), bh = __float2bfloat16(b);
    return (unsigned int)__bfloat16_as_ushort(ah) |
           ((unsigned int)__bfloat16_as_ushort(bh) << 16);
}

#define MMA_BF16(c, A, B0, B1)                                              \
    asm volatile("mma.sync.aligned.m16n8k16.row.col.f32.bf16.bf16.f32 "     \
                 "{%0,%1,%2,%3}, {%4,%5,%6,%7}, {%8,%9}, {%0,%1,%2,%3};"    \
                 : "+f"(c[0]), "+f"(c[1]), "+f"(c[2]), "+f"(c[3])           \
                 : "r"(A.x), "r"(A.y), "r"(A.z), "r"(A.w), "r"(B0), "r"(B1))

__global__ __launch_bounds__(NTHREADS, 1)
void lstm_mma_kernel(
    const float* __restrict__ seq,  const float* __restrict__ W_ih,
    const float* __restrict__ W_hh, const float* __restrict__ b_ih,
    const float* __restrict__ b_hh, const float* __restrict__ fc1w,
    const float* __restrict__ fc1b, const float* __restrict__ fc2w,
    const float* __restrict__ fc2b, float* __restrict__ out)
{
    extern __shared__ unsigned char wsm[];                 // 128KB W fragments
    __shared__ __align__(16) float stage[8][16][18];       // per-warp h repack tile
    __shared__ __align__(16) float4 sm_wih[16], sm_bias[16];
    __shared__ __align__(16) float hs[4][HID];             // fc1 tail

    const int tid  = threadIdx.x;
    const int cta  = blockIdx.x;
    const int gid  = cta * NTHREADS + tid;
    const int lane = tid & 31;
    const int wti  = tid >> 5;
    const int gq   = lane >> 2;
    const int tg   = lane & 3;

    // ---- prep: W fragments (split + gate-interleave reorder). col n -> gate/unit:
    // blk=n/16, w16=n%16, gate=((w16>>3)<<1)|(w16&1), unit=blk*4+((w16&7)>>1)
    for (int it = gid; it < 256 * 32 * 32; it += GSZ) {
        int ln  = it & 31;
        int k16 = (it >> 5) & 31;
        int n8  = it >> 10;
        int n   = n8 * 8 + (ln >> 2);
        int w16 = n & 15;
        int gate = ((w16 >> 3) << 1) | (w16 & 1);
        int unit = (n >> 4) * 4 + ((w16 & 7) >> 1);
        const float* wr = W_hh + (gate * HID + unit) * HID + k16 * 16 + ((ln & 3) << 1);
        float2 p0 = *(const float2*)wr;
        float2 p1 = *(const float2*)(wr + 8);
        float h0x = __bfloat162float(__float2bfloat16(p0.x));
        float h0y = __bfloat162float(__float2bfloat16(p0.y));
        float h1x = __bfloat162float(__float2bfloat16(p1.x));
        float h1y = __bfloat162float(__float2bfloat16(p1.y));
        uint4 v;
        v.x = pack2(p0.x, p0.y);
        v.y = pack2(p1.x, p1.y);
        v.z = pack2(p0.x - h0x, p0.y - h0y);
        v.w = pack2(p1.x - h1x, p1.y - h1y);
        *(uint4*)(g_Wfrag + (((n8 << 5) + k16) << 9) + ln * 16) = v;
    }
    {
        uint4 z = make_uint4(0, 0, 0, 0);
        uint4* hz = (uint4*)g_hfrag[0];
        for (int e = gid; e < (1 << 16); e += GSZ) hz[e] = z;
    }
    gridbar();

    // ---- per-CTA geometry ----
    const int tileM = cta >> 5;            // 0..3
    const int tileN = cta & 31;            // 0..31
    const int b0    = tileM * 128;
    const int m16g  = tileM * 8 + wti;

    // copy this CTA's W fragments to smem (once; smem k16-major)
    {
        uint4* s4 = (uint4*)wsm;
        const uint4* g4 = (const uint4*)g_Wfrag;
        for (int e = tid; e < WSMEM_BYTES / 16; e += NTHREADS) {
            int w = e & 31, c = e >> 5;
            int kt = c >> 3, j = c & 7;
            s4[e] = __ldcg(&g4[(((tileN * 8 + j) << 5) + kt) * 32 + w]);
        }
    }
    for (int e = tid; e < 64; e += NTHREADS) {
        int u = e >> 2, g = e & 3;
        int ku = tileN * 16 + u;
        ((float*)sm_wih)[e]  = W_ih[g * HID + ku];
        ((float*)sm_bias)[e] = b_ih[g * HID + ku] + b_hh[g * HID + ku];
    }
    __syncthreads();

    float creg[2][4];
    #pragma unroll
    for (int r = 0; r < 2; ++r)
        #pragma unroll
        for (int j = 0; j < 4; ++j) creg[r][j] = 0.0f;

    const int row_base = b0 + wti * 16 + gq;

    // ---- recurrent loop ----
    for (int t = 0; t < TLEN; ++t) {
        const unsigned char* hin  = g_hfrag[t & 1];
        unsigned char*       hout = g_hfrag[(t + 1) & 1];
        const unsigned char* abase = hin + ((size_t)(m16g * 32) << 10) + lane * 16;
        const unsigned char* wbase = wsm + lane * 16;

        float acc[8][4];
        #pragma unroll
        for (int j = 0; j < 8; ++j)
            #pragma unroll
            for (int c = 0; c < 4; ++c) acc[j][c] = 0.0f;

        // A slots (even/odd kt), B double buffer (even/odd kt)
        uint4 ahA, alA, ahB, alB;
        uint4 bwA[8], bwB[8];
        ahA = __ldcg((const uint4*)(abase));
        alA = __ldcg((const uint4*)(abase + 512));
        ahB = __ldcg((const uint4*)(abase + 1024));
        alB = __ldcg((const uint4*)(abase + 1536));
        #pragma unroll
        for (int j = 0; j < 8; ++j)
            bwA[j] = *(const uint4*)(wbase + (j << 9));

        #pragma unroll 1
        for (int kt = 0; kt < 32; kt += 2) {
            // ---- even kt: consume bwA/ahA/alA; prefetch bwB for kt+1 ----
            #pragma unroll
            for (int j = 0; j < 8; ++j)
                bwB[j] = *(const uint4*)(wbase + (((kt + 1) << 3) + j << 9));
            #pragma unroll
            for (int j = 0; j < 8; ++j) MMA_BF16(acc[j], ahA, bwA[j].x, bwA[j].y); // h_hi*w_hi
            #pragma unroll
            for (int j = 0; j < 8; ++j) MMA_BF16(acc[j], alA, bwA[j].x, bwA[j].y); // h_lo*w_hi
            #pragma unroll
            for (int j = 0; j < 8; ++j) MMA_BF16(acc[j], ahA, bwA[j].z, bwA[j].w); // h_hi*w_lo
            if (kt + 2 < 32) {
                const unsigned char* p = abase + ((size_t)(kt + 2) << 10);
                ahA = __ldcg((const uint4*)p);
                alA = __ldcg((const uint4*)(p + 512));
                #pragma unroll
                for (int j = 0; j < 8; ++j)
                    bwA[j] = *(const uint4*)(wbase + (((kt + 2) << 3) + j << 9));
            }
            // ---- odd kt: consume bwB/ahB/alB ----
            #pragma unroll
            for (int j = 0; j < 8; ++j) MMA_BF16(acc[j], ahB, bwB[j].x, bwB[j].y);
            #pragma unroll
            for (int j = 0; j < 8; ++j) MMA_BF16(acc[j], alB, bwB[j].x, bwB[j].y);
            #pragma unroll
            for (int j = 0; j < 8; ++j) MMA_BF16(acc[j], ahB, bwB[j].z, bwB[j].w);
            if (kt + 3 < 32) {
                const unsigned char* p = abase + ((size_t)(kt + 3) << 10);
                ahB = __ldcg((const uint4*)p);
                alB = __ldcg((const uint4*)(p + 512));
            }
        }

        // ---- epilogue: gates -> c,h ; repack h into A fragments ----
        #pragma unroll
        for (int rh = 0; rh < 2; ++rh) {
            float xv = seq[(row_base + rh * 8) * TLEN + t];
            #pragma unroll
            for (int jj = 0; jj < 4; ++jj) {
                float4 wv = sm_wih[jj * 4 + tg];
                float4 bv = sm_bias[jj * 4 + tg];
                float gi = acc[2*jj  ][rh*2+0] + xv * wv.x + bv.x;
                float gf = acc[2*jj  ][rh*2+1] + xv * wv.y + bv.y;
                float gg = acc[2*jj+1][rh*2+0] + xv * wv.z + bv.z;
                float go = acc[2*jj+1][rh*2+1] + xv * wv.w + bv.w;
                float cc = sigf(gf) * creg[rh][jj] + sigf(gi) * tanhft(gg);
                creg[rh][jj] = cc;
                float hv = sigf(go) * tanhft(cc);
                stage[wti][gq + rh * 8][jj * 4 + tg] = hv;
                if (t == TLEN - 1)
                    g_hfin[(row_base + rh * 8) * HID + tileN * 16 + jj * 4 + tg] = hv;
            }
        }
        __syncwarp();
        unsigned int fhi[4], flo[4];
        #pragma unroll
        for (int r = 0; r < 4; ++r) {
            int m  = gq + (r & 1) * 8;
            int k0 = tg * 2 + (r >> 1) * 8;
            float a = stage[wti][m][k0];
            float b = stage[wti][m][k0 + 1];
            float ah = __bfloat162float(__float2bfloat16(a));
            float bh = __bfloat162float(__float2bfloat16(b));
            fhi[r] = pack2(a, b);
            flo[r] = pack2(a - ah, b - bh);
        }
        unsigned char* op = hout + ((size_t)(m16g * 32 + tileN) << 10) + lane * 16;
        *(uint4*)op         = make_uint4(fhi[0], fhi[1], fhi[2], fhi[3]);
        *(uint4*)(op + 512) = make_uint4(flo[0], flo[1], flo[2], flo[3]);

        gridbar();
    }

    // ---- fc1: hid = relu(h @ fc1w^T + fc1b), 4 batch rows per CTA ----
    {
        int bb = cta * 4;
        for (int e = tid; e < 4 * HID; e += NTHREADS)
            hs[e >> 9][e & 511] = g_hfin[(bb + (e >> 9)) * HID + (e & 511)];
        __syncthreads();
        int n = tid;                         // HALF == 256 == NTHREADS
        const float* wr = fc1w + n * HID;
        float s0 = fc1b[n], s1 = s0, s2 = s0, s3 = s0;
        #pragma unroll 8
        for (int k = 0; k < HID; ++k) {
            float w = wr[k];
            s0 += hs[0][k] * w; s1 += hs[1][k] * w;
            s2 += hs[2][k] * w; s3 += hs[3][k] * w;
        }
        g_hid[(bb + 0) * HALF + n] = fmaxf(s0, 0.0f);
        g_hid[(bb + 1) * HALF + n] = fmaxf(s1, 0.0f);
        g_hid[(bb + 2) * HALF + n] = fmaxf(s2, 0.0f);
        g_hid[(bb + 3) * HALF + n] = fmaxf(s3, 0.0f);
    }
    gridbar();

    // ---- fc2 ----
    for (int o = gid; o < BATCH * TGT; o += GSZ) {
        int b = o / TGT;
        int tt = o - b * TGT;
        const float* hr = g_hid + b * HALF;
        const float* wr = fc2w + tt * HALF;
        float s = fc2b[tt];
        #pragma unroll 8
        for (int k = 0; k < HALF; ++k) s += hr[k] * wr[k];
        out[o] = s;
    }
}

extern "C" void kernel_launch(void* const* d_in, const int* in_sizes, int n_in,
                              void* d_out, int out_size) {
    (void)in_sizes; (void)n_in; (void)out_size;
    cudaFuncSetAttribute(lstm_mma_kernel,
                         cudaFuncAttributeMaxDynamicSharedMemorySize, WSMEM_BYTES);
    lstm_mma_kernel<<<NCTAS, NTHREADS, WSMEM_BYTES>>>(
        (const float*)d_in[0], (const float*)d_in[1], (const float*)d_in[2],
        (const float*)d_in[3], (const float*)d_in[4], (const float*)d_in[5],
        (const float*)d_in[6], (const float*)d_in[7], (const float*)d_in[8],
        (float*)d_out);
}

// round 9
// speedup vs baseline: 1.5934x; 1.2318x over previous
#include <cuda_runtime.h>
#include <cuda_bf16.h>

#define BATCH 512
#define TLEN  256
#define HID   512
#define HALF  256
#define TGT   28

#define NTHREADS 256
#define NCTAS 256
#define GSZ (NCTAS * NTHREADS)
#define WSMEM_BYTES 65536   // 32 k16 x 4 n8 x 512B (hi+lo W fragments)

// ---------------- device scratch ----------------
// A(h) fragments per (m16,k16): 1024B = [hi: lane*16][lo: +512 + lane*16]
__device__ __align__(16) unsigned char g_hfrag[2][1 << 20];
// B(W) fragments per (n8,k16): 512B = lane*16 : {hi_r0, hi_r1, lo_r0, lo_r1}
__device__ __align__(16) unsigned char g_Wfrag[4 << 20];
__device__ __align__(16) float g_hfin[BATCH * HID];
__device__ unsigned int g_barcnt0;
__device__ volatile unsigned int g_bargen0;
__device__ unsigned int g_gcnt[128];          // group g uses slot g*32 (128B apart)
__device__ volatile unsigned int g_ggen[128];

// full-grid barrier (prep only)
__device__ __forceinline__ void gridbar0() {
    __threadfence();
    __syncthreads();
    if (threadIdx.x == 0) {
        unsigned int gen = g_bargen0;
        if (atomicAdd(&g_barcnt0, 1u) == NCTAS - 1u) {
            g_barcnt0 = 0u;
            __threadfence();
            g_bargen0 = gen + 1u;
        } else {
            while (g_bargen0 == gen) { }
            __threadfence();   // acquire (+ L1 invalidate on sm_103a)
        }
    }
    __syncthreads();
}

// 64-CTA group barrier (per LSTM step); group = tileM
__device__ __forceinline__ void groupbar(int grp) {
    __threadfence();           // release: h-fragment STGs visible
    __syncthreads();
    if (threadIdx.x == 0) {
        volatile unsigned int* genp = &g_ggen[grp * 32];
        unsigned int gen = *genp;
        if (atomicAdd(&g_gcnt[grp * 32], 1u) == 63u) {
            g_gcnt[grp * 32] = 0u;
            __threadfence();
            *genp = gen + 1u;
        } else {
            while (*genp == gen) { }
        }
        __threadfence();       // acquire: emits CCTL.IVALL -> L1 safe for plain LDG
    }
    __syncthreads();
}

__device__ __forceinline__ float sigf(float x)  { return 1.0f / (1.0f + __expf(-x)); }
__device__ __forceinline__ float tanhft(float x){ return 1.0f - 2.0f / (__expf(2.0f * x) + 1.0f); }

__device__ __forceinline__ unsigned int pack2(float a, float b) {
    __nv_bfloat16 ah = __float2bfloat16(a), bh = __float2bfloat16(b);
    return (unsigned int)__bfloat16_as_ushort(ah) |
           ((unsigned int)__bfloat16_as_ushort(bh) << 16);
}

#define MMA_BF16(c, A, B0, B1)                                              \
    asm volatile("mma.sync.aligned.m16n8k16.row.col.f32.bf16.bf16.f32 "     \
                 "{%0,%1,%2,%3}, {%4,%5,%6,%7}, {%8,%9}, {%0,%1,%2,%3};"    \
                 : "+f"(c[0]), "+f"(c[1]), "+f"(c[2]), "+f"(c[3])           \
                 : "r"(A.x), "r"(A.y), "r"(A.z), "r"(A.w), "r"(B0), "r"(B1))

__global__ __launch_bounds__(NTHREADS, 2)
void lstm_mma_kernel(
    const float* __restrict__ seq,  const float* __restrict__ W_ih,
    const float* __restrict__ W_hh, const float* __restrict__ b_ih,
    const float* __restrict__ b_hh, const float* __restrict__ fc1w,
    const float* __restrict__ fc1b, const float* __restrict__ fc2w,
    const float* __restrict__ fc2b, float* __restrict__ out)
{
    extern __shared__ unsigned char wsm[];                 // 64KB W fragments
    __shared__ __align__(16) float stage[8][16][10];       // per-warp h repack tile
    __shared__ __align__(16) float4 sm_wih[8], sm_bias[8];
    __shared__ __align__(16) float hs[2][HID];             // fc1 input rows
    __shared__ __align__(16) float sm_hid[2][HALF];        // fc1 output rows

    const int tid  = threadIdx.x;
    const int cta  = blockIdx.x;
    const int gid  = cta * NTHREADS + tid;
    const int lane = tid & 31;
    const int wti  = tid >> 5;
    const int gq   = lane >> 2;
    const int tg   = lane & 3;

    // ---- prep: W fragments (split + gate-interleave reorder). col n -> gate/unit:
    // blk=n/16, w16=n%16, gate=((w16>>3)<<1)|(w16&1), unit=blk*4+((w16&7)>>1)
    for (int it = gid; it < 256 * 32 * 32; it += GSZ) {
        int ln  = it & 31;
        int k16 = (it >> 5) & 31;
        int n8  = it >> 10;
        int n   = n8 * 8 + (ln >> 2);
        int w16 = n & 15;
        int gate = ((w16 >> 3) << 1) | (w16 & 1);
        int unit = (n >> 4) * 4 + ((w16 & 7) >> 1);
        const float* wr = W_hh + (gate * HID + unit) * HID + k16 * 16 + ((ln & 3) << 1);
        float2 p0 = *(const float2*)wr;
        float2 p1 = *(const float2*)(wr + 8);
        float h0x = __bfloat162float(__float2bfloat16(p0.x));
        float h0y = __bfloat162float(__float2bfloat16(p0.y));
        float h1x = __bfloat162float(__float2bfloat16(p1.x));
        float h1y = __bfloat162float(__float2bfloat16(p1.y));
        uint4 v;
        v.x = pack2(p0.x, p0.y);
        v.y = pack2(p1.x, p1.y);
        v.z = pack2(p0.x - h0x, p0.y - h0y);
        v.w = pack2(p1.x - h1x, p1.y - h1y);
        *(uint4*)(g_Wfrag + (((n8 << 5) + k16) << 9) + ln * 16) = v;
    }
    {
        uint4 z = make_uint4(0, 0, 0, 0);
        uint4* hz = (uint4*)g_hfrag[0];
        for (int e = gid; e < (1 << 16); e += GSZ) hz[e] = z;
    }
    gridbar0();

    // ---- per-CTA geometry ----
    const int tileM = cta & 3;             // co-resident CTAs (bid, bid+148) share tileM
    const int tileN = cta >> 2;            // 0..63  (32 gate-cols = 8 units)
    const int m16g  = tileM * 8 + wti;
    const int k16w  = tileN >> 1;          // which k16 fragment this CTA co-writes
    const int khalf = tileN & 1;           // which 8-byte half of each lane slot

    // copy this CTA's W fragments to smem (once; k16-major: (kt*4 + j) chunks)
    {
        uint4* s4 = (uint4*)wsm;
        const uint4* g4 = (const uint4*)g_Wfrag;
        for (int e = tid; e < WSMEM_BYTES / 16; e += NTHREADS) {
            int w = e & 31, c = e >> 5;
            int kt = c >> 2, j = c & 3;
            s4[e] = __ldcg(&g4[(((tileN * 4 + j) << 5) + kt) * 32 + w]);
        }
    }
    for (int e = tid; e < 32; e += NTHREADS) {
        int u = e >> 2, g = e & 3;
        int ku = tileN * 8 + u;
        ((float*)sm_wih)[e]  = W_ih[g * HID + ku];
        ((float*)sm_bias)[e] = b_ih[g * HID + ku] + b_hh[g * HID + ku];
    }
    __syncthreads();

    float creg[2][2];                      // [rh][block b]
    creg[0][0] = creg[0][1] = creg[1][0] = creg[1][1] = 0.0f;

    const int row_base = tileM * 128 + wti * 16 + gq;

    // ---- recurrent loop ----
    for (int t = 0; t < TLEN; ++t) {
        const unsigned char* hin  = g_hfrag[t & 1];
        unsigned char*       hout = g_hfrag[(t + 1) & 1];
        const unsigned char* abase = hin + ((size_t)(m16g * 32) << 10) + lane * 16;
        const unsigned char* wbase = wsm + lane * 16;

        float acc[4][4];
        #pragma unroll
        for (int j = 0; j < 4; ++j)
            #pragma unroll
            for (int c = 0; c < 4; ++c) acc[j][c] = 0.0f;

        uint4 ah[2], al[2];                // slots for even/odd kt (plain LDG -> L1)
        ah[0] = *(const uint4*)(abase);
        al[0] = *(const uint4*)(abase + 512);
        ah[1] = *(const uint4*)(abase + 1024);
        al[1] = *(const uint4*)(abase + 1536);

        #pragma unroll 2
        for (int kt = 0; kt < 32; ++kt) {
            const int s = kt & 1;
            uint4 bw[4];
            #pragma unroll
            for (int j = 0; j < 4; ++j)
                bw[j] = *(const uint4*)(wbase + ((((kt << 2) + j)) << 9));
            #pragma unroll
            for (int j = 0; j < 4; ++j) MMA_BF16(acc[j], ah[s], bw[j].x, bw[j].y); // h_hi*w_hi
            #pragma unroll
            for (int j = 0; j < 4; ++j) MMA_BF16(acc[j], al[s], bw[j].x, bw[j].y); // h_lo*w_hi
            #pragma unroll
            for (int j = 0; j < 4; ++j) MMA_BF16(acc[j], ah[s], bw[j].z, bw[j].w); // h_hi*w_lo
            if (kt + 2 < 32) {
                const unsigned char* p = abase + ((size_t)(kt + 2) << 10);
                ah[s] = *(const uint4*)p;
                al[s] = *(const uint4*)(p + 512);
            }
        }

        // ---- epilogue: gates -> c,h ; stage h ----
        #pragma unroll
        for (int rh = 0; rh < 2; ++rh) {
            float xv = seq[(row_base + rh * 8) * TLEN + t];
            #pragma unroll
            for (int b = 0; b < 2; ++b) {
                float4 wv = sm_wih[b * 4 + tg];
                float4 bv = sm_bias[b * 4 + tg];
                float gi = acc[2*b  ][rh*2+0] + xv * wv.x + bv.x;
                float gf = acc[2*b  ][rh*2+1] + xv * wv.y + bv.y;
                float gg = acc[2*b+1][rh*2+0] + xv * wv.z + bv.z;
                float go = acc[2*b+1][rh*2+1] + xv * wv.w + bv.w;
                float cc = sigf(gf) * creg[rh][b] + sigf(gi) * tanhft(gg);
                creg[rh][b] = cc;
                float hv = sigf(go) * tanhft(cc);
                stage[wti][gq + rh * 8][b * 4 + tg] = hv;
                if (t == TLEN - 1)
                    g_hfin[(row_base + rh * 8) * HID + tileN * 8 + b * 4 + tg] = hv;
            }
        }
        __syncwarp();
        // repack: this CTA supplies k-half 'khalf' of fragment (m16g, k16w)
        {
            float a0 = stage[wti][gq    ][tg * 2];
            float a1 = stage[wti][gq    ][tg * 2 + 1];
            float b0 = stage[wti][gq + 8][tg * 2];
            float b1 = stage[wti][gq + 8][tg * 2 + 1];
            float a0h = __bfloat162float(__float2bfloat16(a0));
            float a1h = __bfloat162float(__float2bfloat16(a1));
            float b0h = __bfloat162float(__float2bfloat16(b0));
            float b1h = __bfloat162float(__float2bfloat16(b1));
            unsigned int hi0 = pack2(a0, a1),         hi1 = pack2(b0, b1);
            unsigned int lo0 = pack2(a0 - a0h, a1 - a1h), lo1 = pack2(b0 - b0h, b1 - b1h);
            unsigned char* op = hout + ((size_t)(m16g * 32 + k16w) << 10)
                                     + lane * 16 + khalf * 8;
            *(uint2*)op         = make_uint2(hi0, hi1);
            *(uint2*)(op + 512) = make_uint2(lo0, lo1);
        }

        groupbar(tileM);
    }

    // ---- fc1: hid = relu(h @ fc1w^T + fc1b), 2 batch rows per CTA ----
    const int bb = tileM * 128 + tileN * 2;     // rows within this CTA's group
    {
        for (int e = tid; e < 2 * HID; e += NTHREADS)
            hs[e >> 9][e & 511] = g_hfin[(bb + (e >> 9)) * HID + (e & 511)];
        __syncthreads();
        int n = tid;                            // HALF == 256 == NTHREADS
        const float* wr = fc1w + n * HID;
        float s0 = fc1b[n], s1 = s0;
        #pragma unroll 8
        for (int k = 0; k < HID; ++k) {
            float w = wr[k];
            s0 += hs[0][k] * w; s1 += hs[1][k] * w;
        }
        sm_hid[0][n] = fmaxf(s0, 0.0f);
        sm_hid[1][n] = fmaxf(s1, 0.0f);
    }
    __syncthreads();

    // ---- fc2 (same CTA, rows bb, bb+1) ----
    for (int i = tid; i < 2 * TGT; i += NTHREADS) {
        int r  = i / TGT;
        int tt = i - r * TGT;
        const float* hr = sm_hid[r];
        const float* wr = fc2w + tt * HALF;
        float s = fc2b[tt];
        #pragma unroll 8
        for (int k = 0; k < HALF; ++k) s += hr[k] * wr[k];
        out[(bb + r) * TGT + tt] = s;
    }
}

extern "C" void kernel_launch(void* const* d_in, const int* in_sizes, int n_in,
                              void* d_out, int out_size) {
    (void)in_sizes; (void)n_in; (void)out_size;
    cudaFuncSetAttribute(lstm_mma_kernel,
                         cudaFuncAttributeMaxDynamicSharedMemorySize, WSMEM_BYTES);
    lstm_mma_kernel<<<NCTAS, NTHREADS, WSMEM_BYTES>>>(
        (const float*)d_in[0], (const float*)d_in[1], (const float*)d_in[2],
        (const float*)d_in[3], (const float*)d_in[4], (const float*)d_in[5],
        (const float*)d_in[6], (const float*)d_in[7], (const float*)d_in[8],
        (float*)d_out);
}